// round 6
// baseline (speedup 1.0000x reference)
#include <cuda_runtime.h>

typedef unsigned long long ull;

#define BN 16
#define TILE 64

__device__ float g_q[25000 * 224];
__device__ float g_k[25000 * 224];
__device__ float g_v[25000 * 224];
__device__ float g_w2p[224 * 224];   // [k][c] = concat(W2r,W2s)[k][c]
__device__ float g_wqT[7168];        // [h][j*32+i]
__device__ float g_wkT[7168];
__device__ float g_wvT[12544];       // [h][j*56+i]

__device__ __forceinline__ float silu_f(float x) { return x / (1.0f + __expf(-x)); }

__device__ __forceinline__ ull fpack2(float lo, float hi) {
    ull u; asm("mov.b64 %0,{%1,%2};" : "=l"(u) : "f"(lo), "f"(hi)); return u;
}
__device__ __forceinline__ void funpack2(ull u, float& lo, float& hi) {
    asm("mov.b64 {%0,%1},%2;" : "=f"(lo), "=f"(hi) : "l"(u));
}
__device__ __forceinline__ void ffma2(ull& d, ull a, ull b) {
    asm("fma.rn.f32x2 %0, %1, %2, %0;" : "+l"(d) : "l"(a), "l"(b));
}

// ---------------------------------------------------------------------------
// prep: zero outputs, concat W2, transpose node weights
__global__ void k_prep(const float* __restrict__ W2r, const float* __restrict__ W2s,
                       const float* __restrict__ Wq, const float* __restrict__ Wk,
                       const float* __restrict__ Wv,
                       float* __restrict__ outx, float* __restrict__ outev, int N)
{
    int gid = blockIdx.x * blockDim.x + threadIdx.x;
    int st = gridDim.x * blockDim.x;
    int nx = N * 224, nz = N * 239;
    for (int i = gid; i < nz; i += st) {
        if (i < nx) outx[i] = 0.f; else outev[i - nx] = 0.f;
    }
    for (int i = gid; i < 224 * 224; i += st) {
        g_w2p[i] = (i < 112 * 224) ? W2r[i] : W2s[i - 112 * 224];
    }
    for (int i = gid; i < 7168; i += st) {
        int h = i >> 10, rem = i & 1023, jj = rem >> 5, ich = rem & 31;
        g_wqT[i] = Wq[h * 1024 + ich * 32 + jj];
        g_wkT[i] = Wk[h * 1024 + ich * 32 + jj];
    }
    for (int i = gid; i < 12544; i += st) {
        int h = i / 3136, rem = i - h * 3136, jj = rem / 56, ich = rem - jj * 56;
        g_wvT[i] = Wv[h * 3136 + ich * 56 + jj];
    }
}

// ---------------------------------------------------------------------------
// node kernel: q = silu(Wq x), k = silu(Wk x), v = Wv x
__global__ void __launch_bounds__(256, 3) k_node(const float* __restrict__ x, int N)
{
    __shared__ float xs[BN * 224];
    int tid = threadIdx.x;
    int nb0 = blockIdx.x * BN;
    int cnt = N - nb0; if (cnt > BN) cnt = BN; if (cnt < 0) cnt = 0;

    for (int idx = tid; idx < BN * 224; idx += 256) {
        int u = idx / 224, f = idx - u * 224;
        xs[idx] = (u < cnt) ? x[(nb0 + u) * 224 + f] : 0.0f;
    }
    __syncthreads();

    if (tid < 224) {
        int h = tid >> 5, iq = tid & 31;
        int hv = tid / 56, iv = tid - hv * 56;
        float aq[BN], ak[BN], av[BN];
#pragma unroll
        for (int u = 0; u < BN; u++) { aq[u] = 0.f; ak[u] = 0.f; av[u] = 0.f; }
#pragma unroll 4
        for (int j = 0; j < 32; j++) {
            float wq = g_wqT[h * 1024 + j * 32 + iq];
            float wk = g_wkT[h * 1024 + j * 32 + iq];
#pragma unroll
            for (int u = 0; u < BN; u++) {
                float xv = xs[u * 224 + h * 32 + j];
                aq[u] += wq * xv; ak[u] += wk * xv;
            }
        }
#pragma unroll 4
        for (int j = 0; j < 56; j++) {
            float wv = g_wvT[hv * 3136 + j * 56 + iv];
#pragma unroll
            for (int u = 0; u < BN; u++) av[u] += wv * xs[u * 224 + hv * 56 + j];
        }
        for (int u = 0; u < cnt; u++) {
            g_q[(nb0 + u) * 224 + tid] = silu_f(aq[u]);
            g_k[(nb0 + u) * 224 + tid] = silu_f(ak[u]);
            g_v[(nb0 + u) * 224 + tid] = av[u];
        }
    }
}

// ---------------------------------------------------------------------------
// edge kernel smem layout (floats), TILE=64, 256 threads, 3 blocks/SM
#define OFF_ACT  0          // 224 * 66 = 14784  (k-major, stride 66)
#define OFF_RBF  14784      // 64*32 = 2048   (phase-A scratch)
#define OFF_TMP  16832      // 64*15 = 960
#define OFF_L0   17792      // 64*3  = 192
#define OFF_ALPH 17984      // 64*7  = 448
#define OFF_CUT  18432      // 64
#define OFF_I    18496      // 64
#define OFF_J    18560      // 64
#define EDGE_SMEM_FLOATS 18624   // 74496 B

__global__ void __launch_bounds__(256, 3) k_edge(
    const float* __restrict__ ev, const float* __restrict__ rbf,
    const float* __restrict__ ylm, const float* __restrict__ cut,
    const int* __restrict__ idx_i, const int* __restrict__ idx_j,
    const float* __restrict__ W1r, const float* __restrict__ b1r,
    const float* __restrict__ b2r,
    const float* __restrict__ W1s, const float* __restrict__ b1s,
    const float* __restrict__ b2s,
    float* __restrict__ outx, float* __restrict__ outev, int P)
{
    extern __shared__ float sm[];
    int* sI = (int*)(sm + OFF_I);
    int* sJ = (int*)(sm + OFF_J);

    int tid = threadIdx.x, tx = tid & 31, ty = tid >> 5;
    int p0 = blockIdx.x * TILE;
    int vend = P - p0; if (vend > TILE) vend = TILE;

    for (int idx = tid; idx < TILE; idx += 256) {
        int p = p0 + idx; bool v = p < P;
        sI[idx] = v ? idx_i[p] : 0;
        sJ[idx] = v ? idx_j[p] : 0;
        sm[OFF_CUT + idx] = v ? cut[p] : 0.f;
    }
    __syncthreads();
    for (int idx = tid; idx < TILE * 32; idx += 256) {
        int e = idx >> 5, j = idx & 31; int p = p0 + e;
        sm[OFF_RBF + idx] = (p < P) ? rbf[p * 32 + j] * sm[OFF_CUT + e] : 0.f;
    }
    for (int idx = tid; idx < TILE * 15; idx += 256) {
        int e = idx / 15, o = idx - e * 15; int p = p0 + e;
        float d = 0.f;
        if (p < P) d = ev[sJ[e] * 15 + o] - ev[sI[e] * 15 + o];
        sm[OFF_TMP + idx] = d * d;
    }
    __syncthreads();
    for (int idx = tid; idx < TILE * 3; idx += 256) {
        int e = idx / 3, dg = idx - e * 3;
        int o0 = (dg == 0) ? 0 : ((dg == 1) ? 3 : 8);
        int o1 = (dg == 0) ? 3 : ((dg == 1) ? 8 : 15);
        float s = 0.f;
        for (int o = o0; o < o1; o++) s += sm[OFF_TMP + e * 15 + o];
        sm[OFF_L0 + idx] = s;
    }
    __syncthreads();

    // ---- Phase A: hidden acts, thread = channel a (0..223), 4 chunks of 16
    if (tid < 224) {
        int a = tid;
        bool isr = (a < 112);
        float b0 = isr ? b1r[a] : b1s[a - 112];
        float ws0 = 0, ws1 = 0, ws2 = 0;
        if (!isr) {
            ws0 = W1s[a - 112]; ws1 = W1s[112 + a - 112]; ws2 = W1s[224 + a - 112];
        }
        for (int ch = 0; ch < 4; ch++) {
            float acc[16];
#pragma unroll
            for (int e = 0; e < 16; e++) acc[e] = b0;
            if (isr) {
#pragma unroll
                for (int j4 = 0; j4 < 8; j4++) {
                    float w0 = W1r[(j4 * 4 + 0) * 112 + a];
                    float w1 = W1r[(j4 * 4 + 1) * 112 + a];
                    float w2v = W1r[(j4 * 4 + 2) * 112 + a];
                    float w3 = W1r[(j4 * 4 + 3) * 112 + a];
#pragma unroll
                    for (int e = 0; e < 16; e++) {
                        float4 r4 = *(const float4*)&sm[OFF_RBF + (ch * 16 + e) * 32 + j4 * 4];
                        acc[e] += r4.x * w0 + r4.y * w1 + r4.z * w2v + r4.w * w3;
                    }
                }
            } else {
#pragma unroll
                for (int e = 0; e < 16; e++) {
                    int ee = ch * 16 + e;
                    acc[e] += sm[OFF_L0 + ee * 3] * ws0 + sm[OFF_L0 + ee * 3 + 1] * ws1
                            + sm[OFF_L0 + ee * 3 + 2] * ws2;
                }
            }
#pragma unroll
            for (int e = 0; e < 16; e++)
                sm[OFF_ACT + a * 66 + ch * 16 + e] = silu_f(acc[e]);
        }
    }
    __syncthreads();

    // ---- Phase B: w = act @ W2cat + b2; weights via L1 (LDG), act via LDS
    // thread: 4 edge-pairs (warp ty -> edges [ty*8, ty*8+8)) x 7 channels
    ull acc2[4][7];
#pragma unroll
    for (int r = 0; r < 7; r++) {
        int c = tx + 32 * r;
        float b2 = b2r[c] + b2s[c];
        ull bb = fpack2(b2, b2);
#pragma unroll
        for (int ep = 0; ep < 4; ep++) acc2[ep][r] = bb;
    }

    {
        const float* wp = g_w2p + tx;
        const float* ab = &sm[OFF_ACT + ty * 8];
#pragma unroll 4
        for (int k = 0; k < 224; k++) {
            const float* wk = wp + k * 224;
            float w0 = __ldg(wk);
            float w1 = __ldg(wk + 32);
            float w2v = __ldg(wk + 64);
            float w3 = __ldg(wk + 96);
            float w4 = __ldg(wk + 128);
            float w5 = __ldg(wk + 160);
            float w6 = __ldg(wk + 192);
            const ull* ap = (const ull*)(ab + k * 66);
            ull a0 = ap[0], a1 = ap[1], a2 = ap[2], a3 = ap[3];
            ull ww;
            ww = fpack2(w0, w0);
            ffma2(acc2[0][0], a0, ww); ffma2(acc2[1][0], a1, ww);
            ffma2(acc2[2][0], a2, ww); ffma2(acc2[3][0], a3, ww);
            ww = fpack2(w1, w1);
            ffma2(acc2[0][1], a0, ww); ffma2(acc2[1][1], a1, ww);
            ffma2(acc2[2][1], a2, ww); ffma2(acc2[3][1], a3, ww);
            ww = fpack2(w2v, w2v);
            ffma2(acc2[0][2], a0, ww); ffma2(acc2[1][2], a1, ww);
            ffma2(acc2[2][2], a2, ww); ffma2(acc2[3][2], a3, ww);
            ww = fpack2(w3, w3);
            ffma2(acc2[0][3], a0, ww); ffma2(acc2[1][3], a1, ww);
            ffma2(acc2[2][3], a2, ww); ffma2(acc2[3][3], a3, ww);
            ww = fpack2(w4, w4);
            ffma2(acc2[0][4], a0, ww); ffma2(acc2[1][4], a1, ww);
            ffma2(acc2[2][4], a2, ww); ffma2(acc2[3][4], a3, ww);
            ww = fpack2(w5, w5);
            ffma2(acc2[0][5], a0, ww); ffma2(acc2[1][5], a1, ww);
            ffma2(acc2[2][5], a2, ww); ffma2(acc2[3][5], a3, ww);
            ww = fpack2(w6, w6);
            ffma2(acc2[0][6], a0, ww); ffma2(acc2[1][6], a1, ww);
            ffma2(acc2[2][6], a2, ww); ffma2(acc2[3][6], a3, ww);
        }
    }

    // ---- Epilogue: alpha[e][r] = cut * sum_c w*q_i*k_j
#pragma unroll
    for (int ep = 0; ep < 4; ep++) {
        int e0 = ty * 8 + 2 * ep, e1 = e0 + 1;
        int i0 = sI[e0], j0 = sJ[e0], i1 = sI[e1], j1 = sJ[e1];
#pragma unroll
        for (int r = 0; r < 7; r++) {
            int c = tx + 32 * r;
            float wlo, whi; funpack2(acc2[ep][r], wlo, whi);
            float s0 = wlo * g_q[i0 * 224 + c] * g_k[j0 * 224 + c];
            float s1 = whi * g_q[i1 * 224 + c] * g_k[j1 * 224 + c];
#pragma unroll
            for (int off = 16; off; off >>= 1) {
                s0 += __shfl_xor_sync(0xffffffffu, s0, off);
                s1 += __shfl_xor_sync(0xffffffffu, s1, off);
            }
            if (tx == 0) {
                sm[OFF_ALPH + e0 * 7 + r] = s0 * sm[OFF_CUT + e0];
                sm[OFF_ALPH + e1 * 7 + r] = s1 * sm[OFF_CUT + e1];
            }
        }
    }
    __syncthreads();

    // ---- Phase C: segment scatter (idx_i sorted)
    if (tid < 224) {
        int h = tid / 56;
        int cur = sI[0]; float acc = 0.f;
#pragma unroll 4
        for (int e = 0; e < vend; e++) {
            int i = sI[e];
            if (i != cur) { atomicAdd(&outx[cur * 224 + tid], acc); acc = 0.f; cur = i; }
            acc += sm[OFF_ALPH + e * 7 + h] * g_v[sJ[e] * 224 + tid];
        }
        atomicAdd(&outx[cur * 224 + tid], acc);
    } else if (tid < 239) {
        int o = tid - 224;
        int dh = (o < 3) ? 4 : ((o < 8) ? 5 : 6);
        int cur = sI[0]; float acc = 0.f;
#pragma unroll 4
        for (int e = 0; e < vend; e++) {
            int i = sI[e];
            if (i != cur) { atomicAdd(&outev[cur * 15 + o], acc); acc = 0.f; cur = i; }
            acc += sm[OFF_ALPH + e * 7 + dh] * ylm[(p0 + e) * 15 + o];
        }
        atomicAdd(&outev[cur * 15 + o], acc);
    }
}

// ---------------------------------------------------------------------------
extern "C" void kernel_launch(void* const* d_in, const int* in_sizes, int n_in,
                              void* d_out, int out_size) {
    const float* x    = (const float*)d_in[0];
    const float* ev   = (const float*)d_in[1];
    const float* rbf  = (const float*)d_in[2];
    const float* ylm  = (const float*)d_in[3];
    const float* cut  = (const float*)d_in[4];
    const int*   idx_i = (const int*)d_in[5];
    const int*   idx_j = (const int*)d_in[6];
    const float* W1r = (const float*)d_in[7];
    const float* b1r = (const float*)d_in[8];
    const float* W2r = (const float*)d_in[9];
    const float* b2r = (const float*)d_in[10];
    const float* W1s = (const float*)d_in[11];
    const float* b1s = (const float*)d_in[12];
    const float* W2s = (const float*)d_in[13];
    const float* b2s = (const float*)d_in[14];
    const float* Wq  = (const float*)d_in[15];
    const float* Wk  = (const float*)d_in[16];
    const float* Wv  = (const float*)d_in[17];

    int N = in_sizes[0] / 224;
    int P = in_sizes[4];
    float* outx  = (float*)d_out;
    float* outev = outx + (size_t)N * 224;

    const int EDGE_SMEM = EDGE_SMEM_FLOATS * 4;  // 74496 B
    cudaFuncSetAttribute(k_edge, cudaFuncAttributeMaxDynamicSharedMemorySize, EDGE_SMEM);

    k_prep<<<512, 256>>>(W2r, W2s, Wq, Wk, Wv, outx, outev, N);
    k_node<<<(N + BN - 1) / BN, 256>>>(x, N);
    k_edge<<<(P + TILE - 1) / TILE, 256, EDGE_SMEM>>>(
        ev, rbf, ylm, cut, idx_i, idx_j,
        W1r, b1r, b2r, W1s, b1s, b2s, outx, outev, P);
}

// round 10
// speedup vs baseline: 1.0344x; 1.0344x over previous
#include <cuda_runtime.h>
#include <cuda_fp16.h>
typedef unsigned long long ull;
typedef unsigned int u32;

#define BN 16
#define TILE 64

__device__ float g_q[25000 * 224];
__device__ float g_k[25000 * 224];
__device__ float g_v[25000 * 224];
__device__ __half g_bthi[224 * 224];  // BT[n][k] = W2cat[k][n], hi part
__device__ __half g_btlo[224 * 224];  // lo part
__device__ float g_wqT[7168];
__device__ float g_wkT[7168];
__device__ float g_wvT[12544];

__device__ __forceinline__ float silu_f(float x) { return x / (1.0f + __expf(-x)); }
__device__ __forceinline__ u32 sptr(const void* p) { return (u32)__cvta_generic_to_shared(p); }

__device__ __forceinline__ void ldmx4(u32& r0, u32& r1, u32& r2, u32& r3, u32 a) {
    asm volatile("ldmatrix.sync.aligned.m8n8.x4.shared.b16 {%0,%1,%2,%3},[%4];"
                 : "=r"(r0), "=r"(r1), "=r"(r2), "=r"(r3) : "r"(a));
}
__device__ __forceinline__ void mma16816(float* c, const u32* a, const u32* b) {
    asm volatile("mma.sync.aligned.m16n8k16.row.col.f32.f16.f16.f32 "
                 "{%0,%1,%2,%3},{%4,%5,%6,%7},{%8,%9},{%0,%1,%2,%3};"
                 : "+f"(c[0]), "+f"(c[1]), "+f"(c[2]), "+f"(c[3])
                 : "r"(a[0]), "r"(a[1]), "r"(a[2]), "r"(a[3]), "r"(b[0]), "r"(b[1]));
}

// ---------------------------------------------------------------------------
__global__ void k_prep(const float* __restrict__ W2r, const float* __restrict__ W2s,
                       const float* __restrict__ Wq, const float* __restrict__ Wk,
                       const float* __restrict__ Wv,
                       float* __restrict__ outx, float* __restrict__ outev, int N)
{
    int gid = blockIdx.x * blockDim.x + threadIdx.x, st = gridDim.x * blockDim.x;
    int nx = N * 224, nz = N * 239;
    for (int i = gid; i < nz; i += st) { if (i < nx) outx[i] = 0.f; else outev[i - nx] = 0.f; }
    for (int t = gid; t < 224 * 224; t += st) {
        int n = t / 224, k = t - n * 224;
        float val = (k < 112) ? W2r[k * 224 + n] : W2s[(k - 112) * 224 + n];
        __half h = __float2half_rn(val);
        g_bthi[t] = h;
        g_btlo[t] = __float2half_rn(val - __half2float(h));
    }
    for (int i = gid; i < 7168; i += st) {
        int h = i >> 10, rem = i & 1023, jj = rem >> 5, ic = rem & 31;
        g_wqT[i] = Wq[h * 1024 + ic * 32 + jj];
        g_wkT[i] = Wk[h * 1024 + ic * 32 + jj];
    }
    for (int i = gid; i < 12544; i += st) {
        int h = i / 3136, rem = i - h * 3136, jj = rem / 56, ic = rem - jj * 56;
        g_wvT[i] = Wv[h * 3136 + ic * 56 + jj];
    }
}

// ---------------------------------------------------------------------------
__global__ void __launch_bounds__(256, 3) k_node(const float* __restrict__ x, int N)
{
    __shared__ float xs[BN * 224];
    int tid = threadIdx.x, nb0 = blockIdx.x * BN;
    int cnt = N - nb0; if (cnt > BN) cnt = BN; if (cnt < 0) cnt = 0;
    for (int idx = tid; idx < BN * 224; idx += 256) {
        int u = idx / 224, f = idx - u * 224;
        xs[idx] = (u < cnt) ? x[(nb0 + u) * 224 + f] : 0.f;
    }
    __syncthreads();
    if (tid < 224) {
        int h = tid >> 5, iq = tid & 31, hv = tid / 56, iv = tid - hv * 56;
        float aq[BN], ak[BN], av[BN];
#pragma unroll
        for (int u = 0; u < BN; u++) { aq[u] = ak[u] = av[u] = 0.f; }
#pragma unroll 4
        for (int j = 0; j < 32; j++) {
            float wq = g_wqT[h * 1024 + j * 32 + iq], wk = g_wkT[h * 1024 + j * 32 + iq];
#pragma unroll
            for (int u = 0; u < BN; u++) {
                float xv = xs[u * 224 + h * 32 + j];
                aq[u] += wq * xv; ak[u] += wk * xv;
            }
        }
#pragma unroll 4
        for (int j = 0; j < 56; j++) {
            float wv = g_wvT[hv * 3136 + j * 56 + iv];
#pragma unroll
            for (int u = 0; u < BN; u++) av[u] += wv * xs[u * 224 + hv * 56 + j];
        }
        for (int u = 0; u < cnt; u++) {
            g_q[(nb0 + u) * 224 + tid] = silu_f(aq[u]);
            g_k[(nb0 + u) * 224 + tid] = silu_f(ak[u]);
            g_v[(nb0 + u) * 224 + tid] = av[u];
        }
    }
}

// ---------------------------------------------------------------------------
// k_edge smem (bytes): ACT_HI 0..29696, ACT_LO 29696..59392 (fp16, stride 232 halves)
// D reuses [0..58368) as fp32 stride 228. Then float scratch after 59392.
#define AH_B   0
#define AL_B   29696
#define RBF_F  14848    // float index = byte 59392/4
#define TMP_F  16896
#define L0_F   17856
#define ALPH_F 18048
#define CUT_F  18496
#define SI_F   18560
#define SJ_F   18624
#define B2_F   18688
#define ESM_BYTES ((18688 + 224) * 4)   // 75648

__global__ void __launch_bounds__(256, 2) k_edge(
    const float* __restrict__ ev, const float* __restrict__ rbf,
    const float* __restrict__ ylm, const float* __restrict__ cut,
    const int* __restrict__ idx_i, const int* __restrict__ idx_j,
    const float* __restrict__ W1r, const float* __restrict__ b1r,
    const float* __restrict__ b2r,
    const float* __restrict__ W1s, const float* __restrict__ b1s,
    const float* __restrict__ b2s,
    float* __restrict__ outx, float* __restrict__ outev, int P)
{
    extern __shared__ float sm[];
    __half* ah = (__half*)((char*)sm + AH_B);
    __half* al = (__half*)((char*)sm + AL_B);
    float* dsm = sm;   // after GEMM, stride 228
    int* sI = (int*)(sm + SI_F); int* sJ = (int*)(sm + SJ_F);

    int tid = threadIdx.x, lane = tid & 31, wid = tid >> 5;
    int p0 = blockIdx.x * TILE;
    int vend = P - p0; if (vend > TILE) vend = TILE;

    for (int idx = tid; idx < TILE; idx += 256) {
        int p = p0 + idx; bool v = p < P;
        sI[idx] = v ? idx_i[p] : 0;
        sJ[idx] = v ? idx_j[p] : 0;
        sm[CUT_F + idx] = v ? cut[p] : 0.f;
    }
    for (int idx = tid; idx < 224; idx += 256) sm[B2_F + idx] = b2r[idx] + b2s[idx];
    __syncthreads();
    for (int idx = tid; idx < TILE * 32; idx += 256) {
        int e = idx >> 5, j = idx & 31; int p = p0 + e;
        sm[RBF_F + idx] = (p < P) ? rbf[p * 32 + j] * sm[CUT_F + e] : 0.f;
    }
    for (int idx = tid; idx < TILE * 15; idx += 256) {
        int e = idx / 15, o = idx - e * 15; int p = p0 + e;
        float d = 0.f;
        if (p < P) d = ev[sJ[e] * 15 + o] - ev[sI[e] * 15 + o];
        sm[TMP_F + idx] = d * d;
    }
    __syncthreads();
    for (int idx = tid; idx < TILE * 3; idx += 256) {
        int e = idx / 3, dg = idx - e * 3;
        int o0 = (dg == 0) ? 0 : ((dg == 1) ? 3 : 8);
        int o1 = (dg == 0) ? 3 : ((dg == 1) ? 8 : 15);
        float s = 0.f;
        for (int o = o0; o < o1; o++) s += sm[TMP_F + e * 15 + o];
        sm[L0_F + idx] = s;
    }
    __syncthreads();

    // Phase A: hidden acts -> fp16 hi/lo in smem [edge][chan], stride 232 halves
    if (tid < 224) {
        int a = tid;
        bool isr = (a < 112);
        float b0 = isr ? b1r[a] : b1s[a - 112];
        float ws0 = 0, ws1 = 0, ws2 = 0;
        if (!isr) { ws0 = W1s[a - 112]; ws1 = W1s[a]; ws2 = W1s[a + 112]; }
        for (int ch = 0; ch < 4; ch++) {
            float acc[16];
#pragma unroll
            for (int e = 0; e < 16; e++) acc[e] = b0;
            if (isr) {
#pragma unroll
                for (int j4 = 0; j4 < 8; j4++) {
                    float w0 = W1r[(j4 * 4 + 0) * 112 + a];
                    float w1 = W1r[(j4 * 4 + 1) * 112 + a];
                    float w2 = W1r[(j4 * 4 + 2) * 112 + a];
                    float w3 = W1r[(j4 * 4 + 3) * 112 + a];
#pragma unroll
                    for (int e = 0; e < 16; e++) {
                        float4 r4 = *(const float4*)&sm[RBF_F + (ch * 16 + e) * 32 + j4 * 4];
                        acc[e] += r4.x * w0 + r4.y * w1 + r4.z * w2 + r4.w * w3;
                    }
                }
            } else {
#pragma unroll
                for (int e = 0; e < 16; e++) {
                    int ee = ch * 16 + e;
                    acc[e] += sm[L0_F + ee * 3] * ws0 + sm[L0_F + ee * 3 + 1] * ws1 + sm[L0_F + ee * 3 + 2] * ws2;
                }
            }
#pragma unroll
            for (int e = 0; e < 16; e++) {
                int ee = ch * 16 + e;
                float v = silu_f(acc[e]);
                __half h = __float2half_rn(v);
                ah[ee * 232 + a] = h;
                al[ee * 232 + a] = __float2half_rn(v - __half2float(h));
            }
        }
    }
    __syncthreads();

    // Phase B: fp16 mma.sync, 3-pass hi/lo. warp = (m16 tile, n112 half)
    int mb = (wid & 3) * 16;
    int nb = (wid >> 2) * 112;
    float acc[56];
#pragma unroll
    for (int i = 0; i < 56; i++) acc[i] = 0.f;

    u32 aAddrH = sptr(ah) + (u32)(((mb + (lane & 15)) * 232 + (lane >> 4) * 8) * 2);
    u32 aAddrL = aAddrH + (u32)AL_B;
    int krow0 = 2 * (lane & 3);
    int ncol = lane >> 2;

    for (int ks = 0; ks < 14; ks++) {
        u32 aH[4], aL[4];
        ldmx4(aH[0], aH[1], aH[2], aH[3], aAddrH + (u32)(ks * 32));
        ldmx4(aL[0], aL[1], aL[2], aL[3], aAddrL + (u32)(ks * 32));
        int kr = ks * 16 + krow0;
#pragma unroll
        for (int g2 = 0; g2 < 2; g2++) {
            u32 bh[7][2], bl[7][2];
#pragma unroll
            for (int t7 = 0; t7 < 7; t7++) {
                int n = nb + (g2 * 7 + t7) * 8 + ncol;
                const __half* bp = g_bthi + n * 224 + kr;
                bh[t7][0] = *(const u32*)bp;
                bh[t7][1] = *(const u32*)(bp + 8);
                const __half* bq = g_btlo + n * 224 + kr;
                bl[t7][0] = *(const u32*)bq;
                bl[t7][1] = *(const u32*)(bq + 8);
            }
#pragma unroll
            for (int t7 = 0; t7 < 7; t7++) {
                float* c = &acc[(g2 * 7 + t7) * 4];
                mma16816(c, aH, bh[t7]);
                mma16816(c, aH, bl[t7]);
                mma16816(c, aL, bh[t7]);
            }
        }
    }
    __syncthreads();   // all A reads done before D overwrites the region

    // store D frags -> dsm[e][n], stride 228 floats
#pragma unroll
    for (int nt = 0; nt < 14; nt++) {
        int n = nb + nt * 8 + 2 * (lane & 3);
        int r0 = mb + (lane >> 2);
        float2* p0f = (float2*)&dsm[r0 * 228 + n];
        p0f[0] = make_float2(acc[nt * 4 + 0], acc[nt * 4 + 1]);
        float2* p1f = (float2*)&dsm[(r0 + 8) * 228 + n];
        p1f[0] = make_float2(acc[nt * 4 + 2], acc[nt * 4 + 3]);
    }
    __syncthreads();

    // Epilogue: alpha[e][g] = cut * sum_c (D+b2)*q_i*k_j (thread = edge)
    if (tid < TILE) {
        int e = tid;
        const float* qp = g_q + (size_t)sI[e] * 224;
        const float* kp = g_k + (size_t)sJ[e] * 224;
        float cv = sm[CUT_F + e];
#pragma unroll 1
        for (int g = 0; g < 7; g++) {
            float s = 0.f;
#pragma unroll
            for (int c4 = 0; c4 < 8; c4++) {
                int c = g * 32 + c4 * 4;
                float4 dv = *(const float4*)&dsm[e * 228 + c];
                float4 q4 = *(const float4*)(qp + c);
                float4 k4 = *(const float4*)(kp + c);
                const float* bp = &sm[B2_F + c];
                s += (dv.x + bp[0]) * q4.x * k4.x;
                s += (dv.y + bp[1]) * q4.y * k4.y;
                s += (dv.z + bp[2]) * q4.z * k4.z;
                s += (dv.w + bp[3]) * q4.w * k4.w;
            }
            sm[ALPH_F + e * 7 + g] = s * cv;
        }
    }
    __syncthreads();

    // Phase C: segment scatter (idx_i sorted)
    if (tid < 224) {
        int h = tid / 56;
        int cur = sI[0]; float a2 = 0.f;
#pragma unroll 4
        for (int e = 0; e < vend; e++) {
            int i = sI[e];
            if (i != cur) { atomicAdd(&outx[cur * 224 + tid], a2); a2 = 0.f; cur = i; }
            a2 += sm[ALPH_F + e * 7 + h] * g_v[(size_t)sJ[e] * 224 + tid];
        }
        atomicAdd(&outx[cur * 224 + tid], a2);
    } else if (tid < 239) {
        int o = tid - 224;
        int dh = (o < 3) ? 4 : ((o < 8) ? 5 : 6);
        int cur = sI[0]; float a2 = 0.f;
#pragma unroll 4
        for (int e = 0; e < vend; e++) {
            int i = sI[e];
            if (i != cur) { atomicAdd(&outev[cur * 15 + o], a2); a2 = 0.f; cur = i; }
            a2 += sm[ALPH_F + e * 7 + dh] * ylm[(size_t)(p0 + e) * 15 + o];
        }
        atomicAdd(&outev[cur * 15 + o], a2);
    }
}

// ---------------------------------------------------------------------------
extern "C" void kernel_launch(void* const* d_in, const int* in_sizes, int n_in,
                              void* d_out, int out_size) {
    const float* x = (const float*)d_in[0];
    const float* ev = (const float*)d_in[1];
    const float* rbf = (const float*)d_in[2];
    const float* ylm = (const float*)d_in[3];
    const float* cut = (const float*)d_in[4];
    const int* idx_i = (const int*)d_in[5];
    const int* idx_j = (const int*)d_in[6];
    const float* W1r = (const float*)d_in[7];
    const float* b1r = (const float*)d_in[8];
    const float* W2r = (const float*)d_in[9];
    const float* b2r = (const float*)d_in[10];
    const float* W1s = (const float*)d_in[11];
    const float* b1s = (const float*)d_in[12];
    const float* W2s = (const float*)d_in[13];
    const float* b2s = (const float*)d_in[14];
    const float* Wq = (const float*)d_in[15];
    const float* Wk = (const float*)d_in[16];
    const float* Wv = (const float*)d_in[17];

    int N = in_sizes[0] / 224;
    int P = in_sizes[4];
    float* outx = (float*)d_out;
    float* outev = outx + (size_t)N * 224;

    cudaFuncSetAttribute(k_edge, cudaFuncAttributeMaxDynamicSharedMemorySize, ESM_BYTES);
    k_prep<<<512, 256>>>(W2r, W2s, Wq, Wk, Wv, outx, outev, N);
    k_node<<<(N + BN - 1) / BN, 256>>>(x, N);
    k_edge<<<(P + TILE - 1) / TILE, 256, ESM_BYTES>>>(
        ev, rbf, ylm, cut, idx_i, idx_j, W1r, b1r, b2r, W1s, b1s, b2s, outx, outev, P);
}

// round 12
// speedup vs baseline: 1.1632x; 1.1245x over previous
#include <cuda_runtime.h>
#include <cuda_fp16.h>
typedef unsigned long long ull;
typedef unsigned int u32;

#define BN 16
#define TILE 64

__device__ float g_q[25000 * 224];
__device__ float g_k[25000 * 224];
__device__ float g_v[25000 * 224];
__device__ __half g_bthi[224 * 224];  // BT[n][k] = W2cat[k][n], hi
__device__ __half g_btlo[224 * 224];  // lo
__device__ float g_wqT[7168];
__device__ float g_wkT[7168];
__device__ float g_wvT[12544];

__device__ __forceinline__ float silu_f(float x) { return x / (1.0f + __expf(-x)); }
__device__ __forceinline__ u32 sptr(const void* p) { return (u32)__cvta_generic_to_shared(p); }

__device__ __forceinline__ void ldmx4(u32& r0, u32& r1, u32& r2, u32& r3, u32 a) {
    asm volatile("ldmatrix.sync.aligned.m8n8.x4.shared.b16 {%0,%1,%2,%3},[%4];"
                 : "=r"(r0), "=r"(r1), "=r"(r2), "=r"(r3) : "r"(a));
}
__device__ __forceinline__ void mma16816(float* c, const u32* a, u32 b0, u32 b1) {
    asm volatile("mma.sync.aligned.m16n8k16.row.col.f32.f16.f16.f32 "
                 "{%0,%1,%2,%3},{%4,%5,%6,%7},{%8,%9},{%0,%1,%2,%3};"
                 : "+f"(c[0]), "+f"(c[1]), "+f"(c[2]), "+f"(c[3])
                 : "r"(a[0]), "r"(a[1]), "r"(a[2]), "r"(a[3]), "r"(b0), "r"(b1));
}
__device__ __forceinline__ void cp16(u32 d, const void* s) {
    asm volatile("cp.async.cg.shared.global [%0],[%1],16;" :: "r"(d), "l"(s));
}

__global__ void k_nop() {}

// ---------------------------------------------------------------------------
__global__ void k_prep(const float* __restrict__ W2r, const float* __restrict__ W2s,
                       const float* __restrict__ Wq, const float* __restrict__ Wk,
                       const float* __restrict__ Wv,
                       float* __restrict__ outx, float* __restrict__ outev, int N)
{
    int gid = blockIdx.x * blockDim.x + threadIdx.x, st = gridDim.x * blockDim.x;
    int nx = N * 224, nz = N * 239;
    for (int i = gid; i < nz; i += st) { if (i < nx) outx[i] = 0.f; else outev[i - nx] = 0.f; }
    for (int t = gid; t < 224 * 224; t += st) {
        int n = t / 224, k = t - n * 224;
        float val = (k < 112) ? W2r[k * 224 + n] : W2s[(k - 112) * 224 + n];
        __half h = __float2half_rn(val);
        g_bthi[t] = h;
        g_btlo[t] = __float2half_rn(val - __half2float(h));
    }
    for (int i = gid; i < 7168; i += st) {
        int h = i >> 10, rem = i & 1023, jj = rem >> 5, ic = rem & 31;
        g_wqT[i] = Wq[h * 1024 + ic * 32 + jj];
        g_wkT[i] = Wk[h * 1024 + ic * 32 + jj];
    }
    for (int i = gid; i < 12544; i += st) {
        int h = i / 3136, rem = i - h * 3136, jj = rem / 56, ic = rem - jj * 56;
        g_wvT[i] = Wv[h * 3136 + ic * 56 + jj];
    }
}

// ---------------------------------------------------------------------------
__global__ void __launch_bounds__(256, 3) k_node(const float* __restrict__ x, int N)
{
    __shared__ float xs[BN * 224];
    int tid = threadIdx.x, nb0 = blockIdx.x * BN;
    int cnt = N - nb0; if (cnt > BN) cnt = BN; if (cnt < 0) cnt = 0;
    for (int idx = tid; idx < BN * 224; idx += 256) {
        int u = idx / 224, f = idx - u * 224;
        xs[idx] = (u < cnt) ? x[(nb0 + u) * 224 + f] : 0.f;
    }
    __syncthreads();
    if (tid < 224) {
        int h = tid >> 5, iq = tid & 31, hv = tid / 56, iv = tid - hv * 56;
        float aq[BN], ak[BN], av[BN];
#pragma unroll
        for (int u = 0; u < BN; u++) { aq[u] = ak[u] = av[u] = 0.f; }
#pragma unroll 4
        for (int j = 0; j < 32; j++) {
            float wq = g_wqT[h * 1024 + j * 32 + iq], wk = g_wkT[h * 1024 + j * 32 + iq];
#pragma unroll
            for (int u = 0; u < BN; u++) {
                float xv = xs[u * 224 + h * 32 + j];
                aq[u] += wq * xv; ak[u] += wk * xv;
            }
        }
#pragma unroll 4
        for (int j = 0; j < 56; j++) {
            float wv = g_wvT[hv * 3136 + j * 56 + iv];
#pragma unroll
            for (int u = 0; u < BN; u++) av[u] += wv * xs[u * 224 + hv * 56 + j];
        }
        for (int u = 0; u < cnt; u++) {
            g_q[(nb0 + u) * 224 + tid] = silu_f(aq[u]);
            g_k[(nb0 + u) * 224 + tid] = silu_f(ak[u]);
            g_v[(nb0 + u) * 224 + tid] = av[u];
        }
    }
}

// ---------------------------------------------------------------------------
// smem: ACT_HI [0,29696)B, ACT_LO [29696,59392)B fp16 stride 232 halves;
// D reuses [0,58368) fp32 stride 228. Float scratch after. B chunks at BB_B.
#define AH_B   0
#define AL_B   29696
#define RBF_F  14848
#define TMP_F  16896
#define L0_F   17856
#define ALPH_F 18048
#define CUT_F  18496
#define SI_F   18560
#define SJ_F   18624
#define B2_F   18688
#define BB_B   75648            // 2 stages x (7168 hi + 7168 lo) = 28672 B
#define ESM_BYTES (75648 + 28672)

// stage chunk ks (16 k-cols of BT) into buffer buf: [n][16 halves], stride 32B
__device__ __forceinline__ void issue_chunk(u32 bBase, int buf, int ks, int tid) {
    u32 dst0 = bBase + (u32)(buf * 14336);
    for (int idx = tid; idx < 896; idx += 256) {
        int half = idx / 448, i = idx - half * 448;
        int n = i >> 1, s = i & 1;
        const __half* src = (half ? g_btlo : g_bthi) + n * 224 + ks * 16 + s * 8;
        cp16(dst0 + (u32)(half * 7168 + n * 32 + s * 16), src);
    }
}

__global__ void __launch_bounds__(256, 2) k_edge(
    const float* __restrict__ ev, const float* __restrict__ rbf,
    const float* __restrict__ ylm, const float* __restrict__ cut,
    const int* __restrict__ idx_i, const int* __restrict__ idx_j,
    const float* __restrict__ W1r, const float* __restrict__ b1r,
    const float* __restrict__ b2r,
    const float* __restrict__ W1s, const float* __restrict__ b1s,
    const float* __restrict__ b2s,
    float* __restrict__ outx, float* __restrict__ outev, int P)
{
    extern __shared__ float sm[];
    __half* ah = (__half*)((char*)sm + AH_B);
    __half* al = (__half*)((char*)sm + AL_B);
    float* dsm = sm;
    int* sI = (int*)(sm + SI_F); int* sJ = (int*)(sm + SJ_F);

    int tid = threadIdx.x, lane = tid & 31, wid = tid >> 5;
    int p0 = blockIdx.x * TILE;
    int vend = P - p0; if (vend > TILE) vend = TILE;
    u32 bBase = sptr((char*)sm + BB_B);

    issue_chunk(bBase, 0, 0, tid);                 // prefetch chunk 0
    asm volatile("cp.async.commit_group;");

    for (int idx = tid; idx < TILE; idx += 256) {
        int p = p0 + idx; bool v = p < P;
        sI[idx] = v ? idx_i[p] : 0;
        sJ[idx] = v ? idx_j[p] : 0;
        sm[CUT_F + idx] = v ? cut[p] : 0.f;
    }
    for (int idx = tid; idx < 224; idx += 256) sm[B2_F + idx] = b2r[idx] + b2s[idx];
    __syncthreads();
    for (int idx = tid; idx < TILE * 32; idx += 256) {
        int e = idx >> 5, j = idx & 31; int p = p0 + e;
        sm[RBF_F + idx] = (p < P) ? rbf[p * 32 + j] * sm[CUT_F + e] : 0.f;
    }
    for (int idx = tid; idx < TILE * 15; idx += 256) {
        int e = idx / 15, o = idx - e * 15; int p = p0 + e;
        float d = 0.f;
        if (p < P) d = ev[sJ[e] * 15 + o] - ev[sI[e] * 15 + o];
        sm[TMP_F + idx] = d * d;
    }
    __syncthreads();
    for (int idx = tid; idx < TILE * 3; idx += 256) {
        int e = idx / 3, dg = idx - e * 3;
        int o0 = (dg == 0) ? 0 : ((dg == 1) ? 3 : 8);
        int o1 = (dg == 0) ? 3 : ((dg == 1) ? 8 : 15);
        float s = 0.f;
        for (int o = o0; o < o1; o++) s += sm[TMP_F + e * 15 + o];
        sm[L0_F + idx] = s;
    }
    __syncthreads();

    // Phase A: hidden acts -> fp16 hi/lo [edge][chan], stride 232 halves
    if (tid < 224) {
        int a = tid;
        bool isr = (a < 112);
        float b0 = isr ? b1r[a] : b1s[a - 112];
        float ws0 = 0, ws1 = 0, ws2 = 0;
        if (!isr) { ws0 = W1s[a - 112]; ws1 = W1s[a]; ws2 = W1s[a + 112]; }
        for (int ch = 0; ch < 4; ch++) {
            float acc[16];
#pragma unroll
            for (int e = 0; e < 16; e++) acc[e] = b0;
            if (isr) {
#pragma unroll
                for (int j4 = 0; j4 < 8; j4++) {
                    float w0 = W1r[(j4 * 4 + 0) * 112 + a];
                    float w1 = W1r[(j4 * 4 + 1) * 112 + a];
                    float w2 = W1r[(j4 * 4 + 2) * 112 + a];
                    float w3 = W1r[(j4 * 4 + 3) * 112 + a];
#pragma unroll
                    for (int e = 0; e < 16; e++) {
                        float4 r4 = *(const float4*)&sm[RBF_F + (ch * 16 + e) * 32 + j4 * 4];
                        acc[e] += r4.x * w0 + r4.y * w1 + r4.z * w2 + r4.w * w3;
                    }
                }
            } else {
#pragma unroll
                for (int e = 0; e < 16; e++) {
                    int ee = ch * 16 + e;
                    acc[e] += sm[L0_F + ee * 3] * ws0 + sm[L0_F + ee * 3 + 1] * ws1 + sm[L0_F + ee * 3 + 2] * ws2;
                }
            }
#pragma unroll
            for (int e = 0; e < 16; e++) {
                int ee = ch * 16 + e;
                float v = silu_f(acc[e]);
                __half h = __float2half_rn(v);
                ah[ee * 232 + a] = h;
                al[ee * 232 + a] = __float2half_rn(v - __half2float(h));
            }
        }
    }
    __syncthreads();

    // Phase B: hi/lo fp16 mma.sync, B chunks staged in smem (double buffer)
    int mb = (wid & 3) * 16;
    int h2 = wid >> 2;                    // n-half (112)
    float acc[56];
#pragma unroll
    for (int i = 0; i < 56; i++) acc[i] = 0.f;

    u32 aAddrH = sptr(ah) + (u32)((((mb + (lane & 15)) * 232 + (lane >> 4) * 8)) * 2);
    u32 aAddrL = aAddrH + (u32)AL_B;
    int l8 = lane & 7, selk = (lane >> 3) & 1, seln = (lane >> 4) & 1;
    u32 bFragOff = (u32)((h2 * 112 + seln * 8 + l8) * 32 + selk * 16);

    for (int ks = 0; ks < 14; ks++) {
        if (ks > 0) __syncthreads();                      // prev compute done -> safe overwrite
        if (ks < 13) issue_chunk(bBase, (ks + 1) & 1, ks + 1, tid);
        asm volatile("cp.async.commit_group;");
        asm volatile("cp.async.wait_group 1;");
        __syncthreads();                                  // chunk ks visible to all

        u32 aH[4], aL[4];
        ldmx4(aH[0], aH[1], aH[2], aH[3], aAddrH + (u32)(ks * 32));
        ldmx4(aL[0], aL[1], aL[2], aL[3], aAddrL + (u32)(ks * 32));
        u32 bh_base = bBase + (u32)((ks & 1) * 14336) + bFragOff;
        u32 bl_base = bh_base + 7168u;
#pragma unroll
        for (int t = 0; t < 7; t++) {
            u32 bh0, bh1, bh2, bh3, bl0, bl1, bl2, bl3;
            ldmx4(bh0, bh1, bh2, bh3, bh_base + (u32)(t * 512));
            ldmx4(bl0, bl1, bl2, bl3, bl_base + (u32)(t * 512));
            float* c0 = &acc[(t * 2 + 0) * 4];
            float* c1 = &acc[(t * 2 + 1) * 4];
            mma16816(c0, aH, bh0, bh1);
            mma16816(c1, aH, bh2, bh3);
            mma16816(c0, aH, bl0, bl1);
            mma16816(c1, aH, bl2, bl3);
            mma16816(c0, aL, bh0, bh1);
            mma16816(c1, aL, bh2, bh3);
        }
    }
    __syncthreads();   // A reads done before D overwrites region

    // store D frags -> dsm[e][n], stride 228
    int nb = h2 * 112;
#pragma unroll
    for (int nt = 0; nt < 14; nt++) {
        int n = nb + nt * 8 + 2 * (lane & 3);
        int r0 = mb + (lane >> 2);
        *(float2*)&dsm[r0 * 228 + n] = make_float2(acc[nt * 4 + 0], acc[nt * 4 + 1]);
        *(float2*)&dsm[(r0 + 8) * 228 + n] = make_float2(acc[nt * 4 + 2], acc[nt * 4 + 3]);
    }
    __syncthreads();

    // Epilogue: alpha[e][g] = cut * sum_c (D+b2)*q_i*k_j (thread = edge)
    if (tid < TILE) {
        int e = tid;
        const float* qp = g_q + (size_t)sI[e] * 224;
        const float* kp = g_k + (size_t)sJ[e] * 224;
        float cv = sm[CUT_F + e];
#pragma unroll 1
        for (int g = 0; g < 7; g++) {
            float s = 0.f;
#pragma unroll
            for (int c4 = 0; c4 < 8; c4++) {
                int c = g * 32 + c4 * 4;
                float4 dv = *(const float4*)&dsm[e * 228 + c];
                float4 q4 = *(const float4*)(qp + c);
                float4 k4 = *(const float4*)(kp + c);
                const float* bp = &sm[B2_F + c];
                s += (dv.x + bp[0]) * q4.x * k4.x;
                s += (dv.y + bp[1]) * q4.y * k4.y;
                s += (dv.z + bp[2]) * q4.z * k4.z;
                s += (dv.w + bp[3]) * q4.w * k4.w;
            }
            sm[ALPH_F + e * 7 + g] = s * cv;
        }
    }
    __syncthreads();

    // Phase C: segment scatter (idx_i sorted)
    if (tid < 224) {
        int h = tid / 56;
        int cur = sI[0]; float a2 = 0.f;
#pragma unroll 4
        for (int e = 0; e < vend; e++) {
            int i = sI[e];
            if (i != cur) { atomicAdd(&outx[cur * 224 + tid], a2); a2 = 0.f; cur = i; }
            a2 += sm[ALPH_F + e * 7 + h] * g_v[(size_t)sJ[e] * 224 + tid];
        }
        atomicAdd(&outx[cur * 224 + tid], a2);
    } else if (tid < 239) {
        int o = tid - 224;
        int dh = (o < 3) ? 4 : ((o < 8) ? 5 : 6);
        int cur = sI[0]; float a2 = 0.f;
#pragma unroll 4
        for (int e = 0; e < vend; e++) {
            int i = sI[e];
            if (i != cur) { atomicAdd(&outev[cur * 15 + o], a2); a2 = 0.f; cur = i; }
            a2 += sm[ALPH_F + e * 7 + dh] * ylm[(size_t)(p0 + e) * 15 + o];
        }
        atomicAdd(&outev[cur * 15 + o], a2);
    }
}

// ---------------------------------------------------------------------------
extern "C" void kernel_launch(void* const* d_in, const int* in_sizes, int n_in,
                              void* d_out, int out_size) {
    const float* x = (const float*)d_in[0];
    const float* ev = (const float*)d_in[1];
    const float* rbf = (const float*)d_in[2];
    const float* ylm = (const float*)d_in[3];
    const float* cut = (const float*)d_in[4];
    const int* idx_i = (const int*)d_in[5];
    const int* idx_j = (const int*)d_in[6];
    const float* W1r = (const float*)d_in[7];
    const float* b1r = (const float*)d_in[8];
    const float* W2r = (const float*)d_in[9];
    const float* b2r = (const float*)d_in[10];
    const float* W1s = (const float*)d_in[11];
    const float* b1s = (const float*)d_in[12];
    const float* W2s = (const float*)d_in[13];
    const float* b2s = (const float*)d_in[14];
    const float* Wq = (const float*)d_in[15];
    const float* Wk = (const float*)d_in[16];
    const float* Wv = (const float*)d_in[17];

    int N = in_sizes[0] / 224;
    int P = in_sizes[4];
    float* outx = (float*)d_out;
    float* outev = outx + (size_t)N * 224;

    cudaFuncSetAttribute(k_edge, cudaFuncAttributeMaxDynamicSharedMemorySize, ESM_BYTES);
    k_nop<<<1, 32>>>();
    k_prep<<<512, 256>>>(W2r, W2s, Wq, Wk, Wv, outx, outev, N);
    k_node<<<(N + BN - 1) / BN, 256>>>(x, N);
    k_edge<<<(P + TILE - 1) / TILE, 256, ESM_BYTES>>>(
        ev, rbf, ylm, cut, idx_i, idx_j, W1r, b1r, b2r, W1s, b1s, b2s, outx, outev, P);
}

// round 13
// speedup vs baseline: 1.2317x; 1.0589x over previous
#include <cuda_runtime.h>
#include <cuda_fp16.h>
typedef unsigned long long ull;
typedef unsigned int u32;

#define BN 16
#define TILE 64

__device__ float g_q[25000 * 224];
__device__ float g_k[25000 * 224];
__device__ float g_v[25000 * 224];
__device__ __half g_bthi[224 * 224];  // BT[n][k] = W2cat[k][n], hi
__device__ __half g_btlo[224 * 224];  // lo
__device__ float g_wqT[7168];
__device__ float g_wkT[7168];
__device__ float g_wvT[12544];

__device__ __forceinline__ float silu_f(float x) { return x / (1.0f + __expf(-x)); }
__device__ __forceinline__ u32 sptr(const void* p) { return (u32)__cvta_generic_to_shared(p); }

__device__ __forceinline__ void ldmx4(u32& r0, u32& r1, u32& r2, u32& r3, u32 a) {
    asm volatile("ldmatrix.sync.aligned.m8n8.x4.shared.b16 {%0,%1,%2,%3},[%4];"
                 : "=r"(r0), "=r"(r1), "=r"(r2), "=r"(r3) : "r"(a));
}
__device__ __forceinline__ void mma16816(float* c, const u32* a, u32 b0, u32 b1) {
    asm volatile("mma.sync.aligned.m16n8k16.row.col.f32.f16.f16.f32 "
                 "{%0,%1,%2,%3},{%4,%5,%6,%7},{%8,%9},{%0,%1,%2,%3};"
                 : "+f"(c[0]), "+f"(c[1]), "+f"(c[2]), "+f"(c[3])
                 : "r"(a[0]), "r"(a[1]), "r"(a[2]), "r"(a[3]), "r"(b0), "r"(b1));
}
__device__ __forceinline__ void cp16(u32 d, const void* s) {
    asm volatile("cp.async.cg.shared.global [%0],[%1],16;" :: "r"(d), "l"(s));
}

__global__ void k_nop() {}

// ---------------------------------------------------------------------------
__global__ void k_prep(const float* __restrict__ W2r, const float* __restrict__ W2s,
                       const float* __restrict__ Wq, const float* __restrict__ Wk,
                       const float* __restrict__ Wv,
                       float* __restrict__ outx, float* __restrict__ outev, int N)
{
    int gid = blockIdx.x * blockDim.x + threadIdx.x, st = gridDim.x * blockDim.x;
    int nx = N * 224, nz = N * 239;
    for (int i = gid; i < nz; i += st) { if (i < nx) outx[i] = 0.f; else outev[i - nx] = 0.f; }
    for (int t = gid; t < 224 * 224; t += st) {
        int n = t / 224, k = t - n * 224;
        float val = (k < 112) ? W2r[k * 224 + n] : W2s[(k - 112) * 224 + n];
        __half h = __float2half_rn(val);
        g_bthi[t] = h;
        g_btlo[t] = __float2half_rn(val - __half2float(h));
    }
    for (int i = gid; i < 7168; i += st) {
        int h = i >> 10, rem = i & 1023, jj = rem >> 5, ic = rem & 31;
        g_wqT[i] = Wq[h * 1024 + ic * 32 + jj];
        g_wkT[i] = Wk[h * 1024 + ic * 32 + jj];
    }
    for (int i = gid; i < 12544; i += st) {
        int h = i / 3136, rem = i - h * 3136, jj = rem / 56, ic = rem - jj * 56;
        g_wvT[i] = Wv[h * 3136 + ic * 56 + jj];
    }
}

// ---------------------------------------------------------------------------
__global__ void __launch_bounds__(256, 3) k_node(const float* __restrict__ x, int N)
{
    __shared__ float xs[BN * 224];
    int tid = threadIdx.x, nb0 = blockIdx.x * BN;
    int cnt = N - nb0; if (cnt > BN) cnt = BN; if (cnt < 0) cnt = 0;
    for (int idx = tid; idx < BN * 224; idx += 256) {
        int u = idx / 224, f = idx - u * 224;
        xs[idx] = (u < cnt) ? x[(nb0 + u) * 224 + f] : 0.f;
    }
    __syncthreads();
    if (tid < 224) {
        int h = tid >> 5, iq = tid & 31, hv = tid / 56, iv = tid - hv * 56;
        float aq[BN], ak[BN], av[BN];
#pragma unroll
        for (int u = 0; u < BN; u++) { aq[u] = ak[u] = av[u] = 0.f; }
#pragma unroll 4
        for (int j = 0; j < 32; j++) {
            float wq = g_wqT[h * 1024 + j * 32 + iq], wk = g_wkT[h * 1024 + j * 32 + iq];
#pragma unroll
            for (int u = 0; u < BN; u++) {
                float xv = xs[u * 224 + h * 32 + j];
                aq[u] += wq * xv; ak[u] += wk * xv;
            }
        }
#pragma unroll 4
        for (int j = 0; j < 56; j++) {
            float wv = g_wvT[hv * 3136 + j * 56 + iv];
#pragma unroll
            for (int u = 0; u < BN; u++) av[u] += wv * xs[u * 224 + hv * 56 + j];
        }
        for (int u = 0; u < cnt; u++) {
            g_q[(nb0 + u) * 224 + tid] = silu_f(aq[u]);
            g_k[(nb0 + u) * 224 + tid] = silu_f(ak[u]);
            g_v[(nb0 + u) * 224 + tid] = av[u];
        }
    }
}

// ---------------------------------------------------------------------------
// smem: ACT_HI [0,29696)B, ACT_LO [29696,59392)B fp16 stride 232; scratch after;
// B chunks double-buffered at BB_B.
#define AH_B   0
#define AL_B   29696
#define RBF_F  14848
#define TMP_F  16896
#define L0_F   17856
#define ALPH_F 18048
#define CUT_F  18496
#define SI_F   18560
#define SJ_F   18624
#define B2_F   18688
#define BB_B   75648            // 2 stages x (7168 hi + 7168 lo) = 28672 B
#define ESM_BYTES (75648 + 28672)

__device__ __forceinline__ void issue_chunk(u32 bBase, int buf, int ks, int tid) {
    u32 dst0 = bBase + (u32)(buf * 14336);
    for (int idx = tid; idx < 896; idx += 256) {
        int half = idx / 448, i = idx - half * 448;
        int n = i >> 1, s = i & 1;
        const __half* src = (half ? g_btlo : g_bthi) + n * 224 + ks * 16 + s * 8;
        cp16(dst0 + (u32)(half * 7168 + n * 32 + s * 16), src);
    }
}

__global__ void __launch_bounds__(256, 2) k_edge(
    const float* __restrict__ ev, const float* __restrict__ rbf,
    const float* __restrict__ ylm, const float* __restrict__ cut,
    const int* __restrict__ idx_i, const int* __restrict__ idx_j,
    const float* __restrict__ W1r, const float* __restrict__ b1r,
    const float* __restrict__ b2r,
    const float* __restrict__ W1s, const float* __restrict__ b1s,
    const float* __restrict__ b2s,
    float* __restrict__ outx, float* __restrict__ outev, int P)
{
    extern __shared__ float sm[];
    __half* ah = (__half*)((char*)sm + AH_B);
    __half* al = (__half*)((char*)sm + AL_B);
    int* sI = (int*)(sm + SI_F); int* sJ = (int*)(sm + SJ_F);

    int tid = threadIdx.x, lane = tid & 31, wid = tid >> 5;
    int p0 = blockIdx.x * TILE;
    int vend = P - p0; if (vend > TILE) vend = TILE;
    u32 bBase = sptr((char*)sm + BB_B);

    issue_chunk(bBase, 0, 0, tid);                 // prefetch chunk 0
    asm volatile("cp.async.commit_group;");

    for (int idx = tid; idx < TILE; idx += 256) {
        int p = p0 + idx; bool v = p < P;
        sI[idx] = v ? idx_i[p] : 0;
        sJ[idx] = v ? idx_j[p] : 0;
        sm[CUT_F + idx] = v ? cut[p] : 0.f;
    }
    for (int idx = tid; idx < 224; idx += 256) sm[B2_F + idx] = b2r[idx] + b2s[idx];
    for (int idx = tid; idx < 448; idx += 256) sm[ALPH_F + idx] = 0.f;
    __syncthreads();
    for (int idx = tid; idx < TILE * 32; idx += 256) {
        int e = idx >> 5, j = idx & 31; int p = p0 + e;
        sm[RBF_F + idx] = (p < P) ? rbf[p * 32 + j] * sm[CUT_F + e] : 0.f;
    }
    for (int idx = tid; idx < TILE * 15; idx += 256) {
        int e = idx / 15, o = idx - e * 15; int p = p0 + e;
        float d = 0.f;
        if (p < P) d = ev[sJ[e] * 15 + o] - ev[sI[e] * 15 + o];
        sm[TMP_F + idx] = d * d;
    }
    __syncthreads();
    for (int idx = tid; idx < TILE * 3; idx += 256) {
        int e = idx / 3, dg = idx - e * 3;
        int o0 = (dg == 0) ? 0 : ((dg == 1) ? 3 : 8);
        int o1 = (dg == 0) ? 3 : ((dg == 1) ? 8 : 15);
        float s = 0.f;
        for (int o = o0; o < o1; o++) s += sm[TMP_F + e * 15 + o];
        sm[L0_F + idx] = s;
    }
    __syncthreads();

    // Phase A: hidden acts -> fp16 hi/lo [edge][chan], stride 232 halves
    if (tid < 224) {
        int a = tid;
        bool isr = (a < 112);
        float b0 = isr ? b1r[a] : b1s[a - 112];
        float ws0 = 0, ws1 = 0, ws2 = 0;
        if (!isr) { ws0 = W1s[a - 112]; ws1 = W1s[a]; ws2 = W1s[a + 112]; }
        for (int ch = 0; ch < 4; ch++) {
            float acc[16];
#pragma unroll
            for (int e = 0; e < 16; e++) acc[e] = b0;
            if (isr) {
#pragma unroll
                for (int j4 = 0; j4 < 8; j4++) {
                    float w0 = W1r[(j4 * 4 + 0) * 112 + a];
                    float w1 = W1r[(j4 * 4 + 1) * 112 + a];
                    float w2 = W1r[(j4 * 4 + 2) * 112 + a];
                    float w3 = W1r[(j4 * 4 + 3) * 112 + a];
#pragma unroll
                    for (int e = 0; e < 16; e++) {
                        float4 r4 = *(const float4*)&sm[RBF_F + (ch * 16 + e) * 32 + j4 * 4];
                        acc[e] += r4.x * w0 + r4.y * w1 + r4.z * w2 + r4.w * w3;
                    }
                }
            } else {
#pragma unroll
                for (int e = 0; e < 16; e++) {
                    int ee = ch * 16 + e;
                    acc[e] += sm[L0_F + ee * 3] * ws0 + sm[L0_F + ee * 3 + 1] * ws1 + sm[L0_F + ee * 3 + 2] * ws2;
                }
            }
#pragma unroll
            for (int e = 0; e < 16; e++) {
                int ee = ch * 16 + e;
                float v = silu_f(acc[e]);
                __half h = __float2half_rn(v);
                ah[ee * 232 + a] = h;
                al[ee * 232 + a] = __float2half_rn(v - __half2float(h));
            }
        }
    }
    __syncthreads();

    // Phase B: hi/lo fp16 mma.sync, B staged in smem (double buffer)
    int mb = (wid & 3) * 16;
    int h2 = wid >> 2;
    int nb = h2 * 112;
    float acc[56];
#pragma unroll
    for (int i = 0; i < 56; i++) acc[i] = 0.f;

    u32 aAddrH = sptr(ah) + (u32)((((mb + (lane & 15)) * 232 + (lane >> 4) * 8)) * 2);
    u32 aAddrL = aAddrH + (u32)AL_B;
    int l8 = lane & 7, selk = (lane >> 3) & 1, seln = (lane >> 4) & 1;
    u32 bFragOff = (u32)((h2 * 112 + seln * 8 + l8) * 32 + selk * 16);

    for (int ks = 0; ks < 14; ks++) {
        if (ks > 0) __syncthreads();
        if (ks < 13) issue_chunk(bBase, (ks + 1) & 1, ks + 1, tid);
        asm volatile("cp.async.commit_group;");
        asm volatile("cp.async.wait_group 1;");
        __syncthreads();

        u32 aH[4], aL[4];
        ldmx4(aH[0], aH[1], aH[2], aH[3], aAddrH + (u32)(ks * 32));
        ldmx4(aL[0], aL[1], aL[2], aL[3], aAddrL + (u32)(ks * 32));
        u32 bh_base = bBase + (u32)((ks & 1) * 14336) + bFragOff;
        u32 bl_base = bh_base + 7168u;
#pragma unroll
        for (int t = 0; t < 7; t++) {
            u32 bh0, bh1, bh2, bh3, bl0, bl1, bl2, bl3;
            ldmx4(bh0, bh1, bh2, bh3, bh_base + (u32)(t * 512));
            ldmx4(bl0, bl1, bl2, bl3, bl_base + (u32)(t * 512));
            float* c0 = &acc[(t * 2 + 0) * 4];
            float* c1 = &acc[(t * 2 + 1) * 4];
            mma16816(c0, aH, bh0, bh1);
            mma16816(c1, aH, bh2, bh3);
            mma16816(c0, aH, bl0, bl1);
            mma16816(c1, aH, bl2, bl3);
            mma16816(c0, aL, bh0, bh1);
            mma16816(c1, aL, bh2, bh3);
        }
    }

    // Fused epilogue: alpha partials straight from MMA fragments.
    // Lane owns edges e0=mb+(lane>>2), e1=e0+8 at cols n = nb + nt*8 + 2*(lane&3).
    {
        int r0 = mb + (lane >> 2);
        int e0 = r0, e1 = r0 + 8;
        const float* q0 = g_q + (size_t)sI[e0] * 224;
        const float* k0 = g_k + (size_t)sJ[e0] * 224;
        const float* q1 = g_q + (size_t)sI[e1] * 224;
        const float* k1 = g_k + (size_t)sJ[e1] * 224;
        int ncol0 = nb + 2 * (lane & 3);
        float s0[4] = {0.f, 0.f, 0.f, 0.f}, s1[4] = {0.f, 0.f, 0.f, 0.f};
        if (h2 == 0) {
#pragma unroll
            for (int nt = 0; nt < 14; nt++) {
                int n = ncol0 + nt * 8;
                int gs = nt >> 2;
                float2 b2v = *(float2*)&sm[B2_F + n];
                float2 qa = *(const float2*)(q0 + n), ka = *(const float2*)(k0 + n);
                float2 qb = *(const float2*)(q1 + n), kb = *(const float2*)(k1 + n);
                s0[gs] += (acc[nt * 4 + 0] + b2v.x) * qa.x * ka.x + (acc[nt * 4 + 1] + b2v.y) * qa.y * ka.y;
                s1[gs] += (acc[nt * 4 + 2] + b2v.x) * qb.x * kb.x + (acc[nt * 4 + 3] + b2v.y) * qb.y * kb.y;
            }
        } else {
#pragma unroll
            for (int nt = 0; nt < 14; nt++) {
                int n = ncol0 + nt * 8;
                int gs = (nt + 2) >> 2;
                float2 b2v = *(float2*)&sm[B2_F + n];
                float2 qa = *(const float2*)(q0 + n), ka = *(const float2*)(k0 + n);
                float2 qb = *(const float2*)(q1 + n), kb = *(const float2*)(k1 + n);
                s0[gs] += (acc[nt * 4 + 0] + b2v.x) * qa.x * ka.x + (acc[nt * 4 + 1] + b2v.y) * qa.y * ka.y;
                s1[gs] += (acc[nt * 4 + 2] + b2v.x) * qb.x * kb.x + (acc[nt * 4 + 3] + b2v.y) * qb.y * kb.y;
            }
        }
#pragma unroll
        for (int off = 1; off <= 2; off <<= 1) {
#pragma unroll
            for (int s = 0; s < 4; s++) {
                s0[s] += __shfl_xor_sync(0xffffffffu, s0[s], off);
                s1[s] += __shfl_xor_sync(0xffffffffu, s1[s], off);
            }
        }
        if ((lane & 3) == 0) {
#pragma unroll
            for (int s = 0; s < 4; s++) {
                int g = s + 3 * h2;
                atomicAdd(&sm[ALPH_F + e0 * 7 + g], s0[s]);
                atomicAdd(&sm[ALPH_F + e1 * 7 + g], s1[s]);
            }
        }
    }
    __syncthreads();

    // Phase C: segment scatter (idx_i sorted); cut folded in here
    if (tid < 224) {
        int h = tid / 56;
        int cur = sI[0]; float a2 = 0.f;
#pragma unroll 4
        for (int e = 0; e < vend; e++) {
            int i = sI[e];
            if (i != cur) { atomicAdd(&outx[cur * 224 + tid], a2); a2 = 0.f; cur = i; }
            a2 += sm[ALPH_F + e * 7 + h] * sm[CUT_F + e] * g_v[(size_t)sJ[e] * 224 + tid];
        }
        atomicAdd(&outx[cur * 224 + tid], a2);
    } else if (tid < 239) {
        int o = tid - 224;
        int dh = (o < 3) ? 4 : ((o < 8) ? 5 : 6);
        int cur = sI[0]; float a2 = 0.f;
#pragma unroll 4
        for (int e = 0; e < vend; e++) {
            int i = sI[e];
            if (i != cur) { atomicAdd(&outev[cur * 15 + o], a2); a2 = 0.f; cur = i; }
            a2 += sm[ALPH_F + e * 7 + dh] * sm[CUT_F + e] * ylm[(size_t)(p0 + e) * 15 + o];
        }
        atomicAdd(&outev[cur * 15 + o], a2);
    }
}

// ---------------------------------------------------------------------------
extern "C" void kernel_launch(void* const* d_in, const int* in_sizes, int n_in,
                              void* d_out, int out_size) {
    const float* x = (const float*)d_in[0];
    const float* ev = (const float*)d_in[1];
    const float* rbf = (const float*)d_in[2];
    const float* ylm = (const float*)d_in[3];
    const float* cut = (const float*)d_in[4];
    const int* idx_i = (const int*)d_in[5];
    const int* idx_j = (const int*)d_in[6];
    const float* W1r = (const float*)d_in[7];
    const float* b1r = (const float*)d_in[8];
    const float* W2r = (const float*)d_in[9];
    const float* b2r = (const float*)d_in[10];
    const float* W1s = (const float*)d_in[11];
    const float* b1s = (const float*)d_in[12];
    const float* W2s = (const float*)d_in[13];
    const float* b2s = (const float*)d_in[14];
    const float* Wq = (const float*)d_in[15];
    const float* Wk = (const float*)d_in[16];
    const float* Wv = (const float*)d_in[17];

    int N = in_sizes[0] / 224;
    int P = in_sizes[4];
    float* outx = (float*)d_out;
    float* outev = outx + (size_t)N * 224;

    cudaFuncSetAttribute(k_edge, cudaFuncAttributeMaxDynamicSharedMemorySize, ESM_BYTES);
    k_nop<<<1, 32>>>();
    k_prep<<<512, 256>>>(W2r, W2s, Wq, Wk, Wv, outx, outev, N);
    k_node<<<(N + BN - 1) / BN, 256>>>(x, N);
    k_edge<<<(P + TILE - 1) / TILE, 256, ESM_BYTES>>>(
        ev, rbf, ylm, cut, idx_i, idx_j, W1r, b1r, b2r, W1s, b1s, b2s, outx, outev, P);
}